// round 1
// baseline (speedup 1.0000x reference)
#include <cuda_runtime.h>

#define BATCH 1024
#define LOG2E 1.4426950408889634f

// ---------------- device scratch (no allocations allowed) ----------------
__device__ float  g_h1[BATCH * 256];   // after layer 1 + lrelu
__device__ float  g_h2[BATCH * 128];   // after layer 2 (pre-BN)
__device__ float  g_mu[128];
__device__ float  g_rs[128];
__device__ float4 g_M4[50 * BATCH];    // M[:, f, 0..3] * log2e, f-major
__device__ float  g_M1[50 * BATCH];    // M[:, f, 4]    * log2e, f-major

__device__ __forceinline__ float lrelu(float v) { return fmaxf(v, 0.2f * v); }

// ---------------- K1: h1 = lrelu(x @ W1 + b1), [1024,256], K=128 ---------
__global__ void __launch_bounds__(256) k1_gemm(const float* __restrict__ x,
                                               const float* __restrict__ W1,
                                               const float* __restrict__ b1) {
    __shared__ float xs[8][128];
    const int t  = threadIdx.x;          // 256 threads = output column
    const int r0 = blockIdx.x * 8;       // 8 rows per block
    for (int n = t; n < 8 * 128; n += 256)
        xs[n >> 7][n & 127] = x[(r0 + (n >> 7)) * 128 + (n & 127)];
    __syncthreads();

    float acc[8];
#pragma unroll
    for (int r = 0; r < 8; r++) acc[r] = 0.f;
#pragma unroll 4
    for (int k = 0; k < 128; k++) {
        const float w = W1[k * 256 + t];
#pragma unroll
        for (int r = 0; r < 8; r++) acc[r] = fmaf(xs[r][k], w, acc[r]);
    }
    const float bb = b1[t];
#pragma unroll
    for (int r = 0; r < 8; r++) g_h1[(r0 + r) * 256 + t] = lrelu(acc[r] + bb);
}

// ---------------- K2: h2 = h1 @ W2 + b2, [1024,128], K=256 ---------------
__global__ void __launch_bounds__(128) k2_gemm(const float* __restrict__ W2,
                                               const float* __restrict__ b2) {
    __shared__ float hs[8][256];
    const int t  = threadIdx.x;          // 128 threads = output column
    const int r0 = blockIdx.x * 8;
    for (int n = t; n < 8 * 256; n += 128)
        hs[n >> 8][n & 255] = g_h1[(r0 + (n >> 8)) * 256 + (n & 255)];
    __syncthreads();

    float acc[8];
#pragma unroll
    for (int r = 0; r < 8; r++) acc[r] = 0.f;
#pragma unroll 4
    for (int k = 0; k < 256; k++) {
        const float w = W2[k * 128 + t];
#pragma unroll
        for (int r = 0; r < 8; r++) acc[r] = fmaf(hs[r][k], w, acc[r]);
    }
    const float bb = b2[t];
#pragma unroll
    for (int r = 0; r < 8; r++) g_h2[(r0 + r) * 128 + t] = acc[r] + bb;
}

// ---------------- K2b: per-column batch stats (mean, rsqrt(var+eps)) -----
__global__ void __launch_bounds__(128) k2b_stats() {
    __shared__ float ssum[128], ssq[128];
    const int c = blockIdx.x, t = threadIdx.x;
    float s = 0.f, q = 0.f;
    for (int r = t; r < BATCH; r += 128) {
        const float v = g_h2[r * 128 + c];
        s += v;
        q = fmaf(v, v, q);
    }
    ssum[t] = s; ssq[t] = q;
    __syncthreads();
    for (int o = 64; o > 0; o >>= 1) {
        if (t < o) { ssum[t] += ssum[t + o]; ssq[t] += ssq[t + o]; }
        __syncthreads();
    }
    if (t == 0) {
        const float mu  = ssum[0] * (1.f / BATCH);
        const float var = ssq[0] * (1.f / BATCH) - mu * mu;  // biased (torch BN)
        g_mu[c] = mu;
        g_rs[c] = rsqrtf(var + 1e-5f);
    }
}

// ---- K3: BN+lrelu -> layer3 -> attention -> M (pre-scaled) + score base --
__global__ void __launch_bounds__(256) k3_feat(const float* __restrict__ gamma,
                                               const float* __restrict__ beta,
                                               const float* __restrict__ W3,
                                               const float* __restrict__ b3,
                                               const float* __restrict__ Wv,
                                               const float* __restrict__ bv,
                                               const float* __restrict__ Wo,
                                               const float* __restrict__ bo,
                                               const float* __restrict__ T,
                                               const float* __restrict__ Ws,
                                               const float* __restrict__ bs,
                                               float* __restrict__ out) {
    __shared__ float hb[128], h3[64], av[64], hh[64], Mrow[250], sp[64];
    const int i = blockIdx.x, t = threadIdx.x;

    if (t < 128) {
        const float v = g_h2[i * 128 + t];
        hb[t] = lrelu(fmaf((v - g_mu[t]) * g_rs[t], gamma[t], beta[t]));
    }
    __syncthreads();

    if (t < 64) {                 // h3 = lrelu(hb @ W3 + b3)
        float s = b3[t];
#pragma unroll 4
        for (int k = 0; k < 128; k++) s = fmaf(hb[k], W3[k * 64 + t], s);
        h3[t] = lrelu(s);
    }
    __syncthreads();

    if (t < 64) {                 // av = h3 @ Wv + bv
        float s = bv[t];
#pragma unroll 4
        for (int k = 0; k < 64; k++) s = fmaf(h3[k], Wv[k * 64 + t], s);
        av[t] = s;
    }
    __syncthreads();

    if (t < 64) {                 // hh = h3 + av @ Wo + bo ; score partial
        float s = bo[t] + h3[t];
#pragma unroll 4
        for (int k = 0; k < 64; k++) s = fmaf(av[k], Wo[k * 64 + t], s);
        hh[t] = s;
        sp[t] = s * Ws[t];
    }
    __syncthreads();

    if (t < 250) {                // M row = hh @ T, pre-scaled by log2(e)
        float s = 0.f;
#pragma unroll 4
        for (int k = 0; k < 64; k++) s = fmaf(hh[k], T[k * 250 + t], s);
        Mrow[t] = s * LOG2E;
    }
    __syncthreads();

    if (t < 50) {                 // pack per-feature vec4 + scalar, f-major
        g_M4[t * BATCH + i] = make_float4(Mrow[t * 5 + 0], Mrow[t * 5 + 1],
                                          Mrow[t * 5 + 2], Mrow[t * 5 + 3]);
        g_M1[t * BATCH + i] = Mrow[t * 5 + 4];
    }
    if (t < 32) {                 // score base = hh . Ws[0:64] + bs
        float v = sp[t] + sp[t + 32];
#pragma unroll
        for (int o = 16; o > 0; o >>= 1) v += __shfl_down_sync(0xffffffffu, v, o);
        if (t == 0) out[i] = v + bs[0];
    }
}

// ---------------- K4: minibatch discrimination (the hot loop) ------------
// grid (8 j-blocks, 50 features), 128 threads; each thread owns one j.
__global__ void __launch_bounds__(128) k4_mbd(const float* __restrict__ Ws,
                                              float* __restrict__ out) {
    __shared__ float4 s4[BATCH];
    __shared__ float  s1[BATCH];
    const int f = blockIdx.y;
    const int t = threadIdx.x;
    const int j = blockIdx.x * 128 + t;

    const float4* __restrict__ M4 = g_M4 + f * BATCH;
    const float*  __restrict__ M1 = g_M1 + f * BATCH;
    for (int i = t; i < BATCH; i += 128) { s4[i] = M4[i]; s1[i] = M1[i]; }
    __syncthreads();

    const float4 m  = s4[j];
    const float  m4 = s1[j];
    float acc = 0.f;
#pragma unroll 4
    for (int i = 0; i < BATCH; i++) {
        const float4 a  = s4[i];          // warp-broadcast LDS.128
        const float  a4 = s1[i];          // warp-broadcast LDS.32
        const float s01 = fabsf(m.x - a.x) + fabsf(m.y - a.y);
        const float s23 = fabsf(m.z - a.z) + fabsf(m.w - a.w);
        float nd = -s01 - s23;            // FADD with neg modifiers
        nd = nd - fabsf(m4 - a4);         // already negated & log2e-scaled
        float e;
        asm("ex2.approx.f32 %0, %1;" : "=f"(e) : "f"(nd));
        acc += e;
    }
    // self term exp2(0)=1 removed; fold o[j,f] * Ws[64+f] into the score
    atomicAdd(&out[j], (acc - 1.f) * Ws[64 + f]);
}

// ---------------- launcher ----------------
extern "C" void kernel_launch(void* const* d_in, const int* in_sizes, int n_in,
                              void* d_out, int out_size) {
    const float* x     = (const float*)d_in[0];
    const float* W1    = (const float*)d_in[1];
    const float* b1    = (const float*)d_in[2];
    const float* W2    = (const float*)d_in[3];
    const float* b2    = (const float*)d_in[4];
    const float* gamma = (const float*)d_in[5];
    const float* beta  = (const float*)d_in[6];
    const float* W3    = (const float*)d_in[7];
    const float* b3    = (const float*)d_in[8];
    const float* Wv    = (const float*)d_in[9];
    const float* bv    = (const float*)d_in[10];
    const float* Wo    = (const float*)d_in[11];
    const float* bo    = (const float*)d_in[12];
    const float* T     = (const float*)d_in[13];
    const float* Ws    = (const float*)d_in[14];
    const float* bs    = (const float*)d_in[15];
    float* out = (float*)d_out;

    k1_gemm<<<128, 256>>>(x, W1, b1);
    k2_gemm<<<128, 128>>>(W2, b2);
    k2b_stats<<<128, 128>>>();
    k3_feat<<<1024, 256>>>(gamma, beta, W3, b3, Wv, bv, Wo, bo, T, Ws, bs, out);
    k4_mbd<<<dim3(8, 50), 128>>>(Ws, out);
}

// round 3
// speedup vs baseline: 1.2217x; 1.2217x over previous
#include <cuda_runtime.h>

#define BATCH 1024
#define LOG2E 1.4426950408889634f

// ---------------- device scratch (no allocations allowed) ----------------
__device__ float  g_h1[BATCH * 256];   // after layer 1 + lrelu
__device__ float  g_h2[BATCH * 128];   // after layer 2 (pre-BN)
__device__ float  g_sum[128];          // per-col sum of h2 (atomic accum)
__device__ float  g_sq[128];           // per-col sum of h2^2
__device__ float4 g_M4[50 * BATCH];    // M[:, f, 0..3] * log2e, f-major
__device__ float  g_M1[50 * BATCH];    // M[:, f, 4]    * log2e, f-major

__device__ __forceinline__ float lrelu(float v) { return fmaxf(v, 0.2f * v); }

// ---------------- K1: h1 = lrelu(x @ W1 + b1), [1024,256], K=128 ---------
__global__ void __launch_bounds__(256) k1_gemm(const float* __restrict__ x,
                                               const float* __restrict__ W1,
                                               const float* __restrict__ b1) {
    __shared__ float xs[8][128];
    const int t  = threadIdx.x;          // 256 threads = output column
    const int r0 = blockIdx.x * 8;       // 8 rows per block
    if (blockIdx.x == 0 && t < 128) { g_sum[t] = 0.f; g_sq[t] = 0.f; }
    for (int n = t; n < 8 * 128; n += 256)
        xs[n >> 7][n & 127] = x[(r0 + (n >> 7)) * 128 + (n & 127)];
    __syncthreads();

    float acc[8];
#pragma unroll
    for (int r = 0; r < 8; r++) acc[r] = 0.f;
#pragma unroll 16
    for (int k = 0; k < 128; k++) {
        const float w = W1[k * 256 + t];
#pragma unroll
        for (int r = 0; r < 8; r++) acc[r] = fmaf(xs[r][k], w, acc[r]);
    }
    const float bb = b1[t];
#pragma unroll
    for (int r = 0; r < 8; r++) g_h1[(r0 + r) * 256 + t] = lrelu(acc[r] + bb);
}

// ------- K2: h2 = h1 @ W2 + b2, [1024,128], K=256 + partial BN stats -----
__global__ void __launch_bounds__(256) k2_gemm(const float* __restrict__ W2,
                                               const float* __restrict__ b2) {
    __shared__ float hs[8][256];
    const int t  = threadIdx.x;
    const int r0 = blockIdx.x * 8;
    for (int n = t; n < 8 * 256; n += 256)
        hs[n >> 8][n & 255] = g_h1[(r0 + (n >> 8)) * 256 + (n & 255)];
    __syncthreads();

    const int c  = t & 127;              // output column
    const int rg = t >> 7;               // 2 groups x 4 rows
    float acc[4];
#pragma unroll
    for (int r = 0; r < 4; r++) acc[r] = 0.f;
#pragma unroll 8
    for (int k = 0; k < 256; k++) {
        const float w = W2[k * 128 + c];
#pragma unroll
        for (int r = 0; r < 4; r++) acc[r] = fmaf(hs[rg * 4 + r][k], w, acc[r]);
    }
    const float bb = b2[c];
    float s = 0.f, q = 0.f;
#pragma unroll
    for (int r = 0; r < 4; r++) {
        const float v = acc[r] + bb;
        g_h2[(r0 + rg * 4 + r) * 128 + c] = v;
        s += v;
        q = fmaf(v, v, q);
    }
    atomicAdd(&g_sum[c], s);
    atomicAdd(&g_sq[c], q);
}

// ---- K3: BN+lrelu -> layer3 -> attention -> M (pre-scaled) + score base --
// 8 rows per block, 256 threads all active per stage.
__global__ void __launch_bounds__(256) k3_feat(const float* __restrict__ gamma,
                                               const float* __restrict__ beta,
                                               const float* __restrict__ W3,
                                               const float* __restrict__ b3,
                                               const float* __restrict__ Wv,
                                               const float* __restrict__ bv,
                                               const float* __restrict__ Wo,
                                               const float* __restrict__ bo,
                                               const float* __restrict__ T,
                                               const float* __restrict__ Ws,
                                               const float* __restrict__ bs,
                                               float* __restrict__ out) {
    __shared__ float hb[8][128], h3s[8][64], avs[8][64], hhs[8][64];
    __shared__ float Mst[8][250];
    const int t  = threadIdx.x;
    const int r0 = blockIdx.x * 8;

    // BN (stats finalized inline from atomically-accumulated sums) + lrelu
#pragma unroll
    for (int qq = 0; qq < 4; qq++) {
        const int e = t + 256 * qq;
        const int r = e >> 7, c = e & 127;
        const float v   = g_h2[(r0 + r) * 128 + c];
        const float mu  = g_sum[c] * (1.f / BATCH);
        const float var = g_sq[c] * (1.f / BATCH) - mu * mu;
        const float rs  = rsqrtf(var + 1e-5f);
        hb[r][c] = lrelu(fmaf((v - mu) * rs, gamma[c], beta[c]));
    }
    __syncthreads();

    const int c  = t & 63;
    const int rg = t >> 6;               // 4 groups x 2 rows
    // stage A: h3 = lrelu(hb @ W3 + b3)
    {
        float a0 = b3[c], a1 = a0;
#pragma unroll 8
        for (int k = 0; k < 128; k++) {
            const float w = W3[k * 64 + c];
            a0 = fmaf(hb[2 * rg][k], w, a0);
            a1 = fmaf(hb[2 * rg + 1][k], w, a1);
        }
        h3s[2 * rg][c] = lrelu(a0);
        h3s[2 * rg + 1][c] = lrelu(a1);
    }
    __syncthreads();
    // stage B: av = h3 @ Wv + bv
    {
        float a0 = bv[c], a1 = a0;
#pragma unroll 8
        for (int k = 0; k < 64; k++) {
            const float w = Wv[k * 64 + c];
            a0 = fmaf(h3s[2 * rg][k], w, a0);
            a1 = fmaf(h3s[2 * rg + 1][k], w, a1);
        }
        avs[2 * rg][c] = a0;
        avs[2 * rg + 1][c] = a1;
    }
    __syncthreads();
    // stage C: hh = h3 + av @ Wo + bo
    {
        float a0 = bo[c] + h3s[2 * rg][c];
        float a1 = bo[c] + h3s[2 * rg + 1][c];
#pragma unroll 8
        for (int k = 0; k < 64; k++) {
            const float w = Wo[k * 64 + c];
            a0 = fmaf(avs[2 * rg][k], w, a0);
            a1 = fmaf(avs[2 * rg + 1][k], w, a1);
        }
        hhs[2 * rg][c] = a0;
        hhs[2 * rg + 1][c] = a1;
    }
    __syncthreads();

    // score base: one warp per row; out[j] = hh . Ws[0:64] + bs
    {
        const int r = t >> 5, l = t & 31;
        float v = hhs[r][l] * Ws[l] + hhs[r][l + 32] * Ws[l + 32];
#pragma unroll
        for (int o = 16; o > 0; o >>= 1) v += __shfl_down_sync(0xffffffffu, v, o);
        if (l == 0) out[r0 + r] = v + bs[0];
    }

    // stage D: M row = hh @ T (pre-scaled by log2 e)
    if (t < 250) {
        float acc[8];
#pragma unroll
        for (int r = 0; r < 8; r++) acc[r] = 0.f;
#pragma unroll 4
        for (int k = 0; k < 64; k++) {
            const float w = T[k * 250 + t];
#pragma unroll
            for (int r = 0; r < 8; r++) acc[r] = fmaf(hhs[r][k], w, acc[r]);
        }
#pragma unroll
        for (int r = 0; r < 8; r++) Mst[r][t] = acc[r] * LOG2E;
    }
    __syncthreads();

    // pack per-feature vec4 + scalar, f-major by row
    for (int idx = t; idx < 400; idx += 256) {
        const int r = idx / 50, f = idx % 50;
        g_M4[f * BATCH + r0 + r] = make_float4(Mst[r][5 * f + 0], Mst[r][5 * f + 1],
                                               Mst[r][5 * f + 2], Mst[r][5 * f + 3]);
        g_M1[f * BATCH + r0 + r] = Mst[r][5 * f + 4];
    }
}

// ------- K4: minibatch discrimination, symmetric pair enumeration --------
// Each unordered pair (i,j), i!=j, visited once; exp added to both rows.
// Tiles: 64x64 pairs, upper-triangular tile grid (136 tiles), 50 features.
// 256 threads = 16x16, each thread a 4x4 pair sub-tile.
__global__ void __launch_bounds__(256) k4_mbd(const float* __restrict__ Ws,
                                              float* __restrict__ out) {
    __shared__ float4 si4[64], sj4[64];
    __shared__ float  si1[64], sj1[64];
    __shared__ float  red[16][132];      // [group][128 row/col slots], padded

    const int f = blockIdx.y;
    const int t = threadIdx.x;

    // decode upper-triangular tile index (16 strips of 64 rows)
    int u = blockIdx.x, ti_s = 0;
    while (u >= 16 - ti_s) { u -= 16 - ti_s; ti_s++; }
    const int tj_s = ti_s + u;
    const int I0 = ti_s * 64, J0 = tj_s * 64;
    const bool diag = (ti_s == tj_s);

    const float4* __restrict__ M4 = g_M4 + f * BATCH;
    const float*  __restrict__ M1 = g_M1 + f * BATCH;
    if (t < 64)       si4[t]       = M4[I0 + t];
    else if (t < 128) si1[t - 64]  = M1[I0 + t - 64];
    else if (t < 192) sj4[t - 128] = M4[J0 + t - 128];
    else              sj1[t - 192] = M1[J0 + t - 192];
    __syncthreads();

    const int ti = t >> 4, tj = t & 15;  // 4 local rows ti*4+a, 4 cols tj*4+b
    float4 mi4[4], mj4[4];
    float  mi1[4], mj1[4];
#pragma unroll
    for (int a = 0; a < 4; a++) {
        mi4[a] = si4[ti * 4 + a]; mi1[a] = si1[ti * 4 + a];
        mj4[a] = sj4[tj * 4 + a]; mj1[a] = sj1[tj * 4 + a];
    }

    float racc[4] = {0.f, 0.f, 0.f, 0.f};
    float cacc[4] = {0.f, 0.f, 0.f, 0.f};
#pragma unroll
    for (int a = 0; a < 4; a++) {
#pragma unroll
        for (int b = 0; b < 4; b++) {
            const float4 A = mi4[a], B = mj4[b];
            float nd = -fabsf(A.x - B.x) - fabsf(A.y - B.y);
            nd = nd - fabsf(A.z - B.z) - fabsf(A.w - B.w);
            nd = nd - fabsf(mi1[a] - mj1[b]);   // already log2e-scaled
            if (!diag || (ti * 4 + a) > (tj * 4 + b)) {
                float e;
                asm("ex2.approx.f32 %0, %1;" : "=f"(e) : "f"(nd));
                racc[a] += e;
                cacc[b] += e;
            }
        }
    }

    // reduce: row sums over tj groups, col sums over ti groups
#pragma unroll
    for (int a = 0; a < 4; a++) red[tj][ti * 4 + a] = racc[a];
#pragma unroll
    for (int b = 0; b < 4; b++) red[ti][64 + tj * 4 + b] = cacc[b];
    __syncthreads();

    if (t < 128) {
        float s = 0.f;
#pragma unroll
        for (int g = 0; g < 16; g++) s += red[g][t];
        const float wf = Ws[64 + f];
        const int target = (t < 64) ? (I0 + t) : (J0 + t - 64);
        atomicAdd(&out[target], s * wf);
    }
}

// ---------------- launcher ----------------
extern "C" void kernel_launch(void* const* d_in, const int* in_sizes, int n_in,
                              void* d_out, int out_size) {
    const float* x     = (const float*)d_in[0];
    const float* W1    = (const float*)d_in[1];
    const float* b1    = (const float*)d_in[2];
    const float* W2    = (const float*)d_in[3];
    const float* b2    = (const float*)d_in[4];
    const float* gamma = (const float*)d_in[5];
    const float* beta  = (const float*)d_in[6];
    const float* W3    = (const float*)d_in[7];
    const float* b3    = (const float*)d_in[8];
    const float* Wv    = (const float*)d_in[9];
    const float* bv    = (const float*)d_in[10];
    const float* Wo    = (const float*)d_in[11];
    const float* bo    = (const float*)d_in[12];
    const float* T     = (const float*)d_in[13];
    const float* Ws    = (const float*)d_in[14];
    const float* bs    = (const float*)d_in[15];
    float* out = (float*)d_out;

    k1_gemm<<<128, 256>>>(x, W1, b1);
    k2_gemm<<<128, 256>>>(W2, b2);
    k3_feat<<<128, 256>>>(gamma, beta, W3, b3, Wv, bv, Wo, bo, T, Ws, bs, out);
    k4_mbd<<<dim3(136, 50), 256>>>(Ws, out);
}